// round 1
// baseline (speedup 1.0000x reference)
#include <cuda_runtime.h>
#include <math.h>

#define Bb 16
#define Ss 2048
#define Tt 1024
#define Ee 256
#define Dd 256

// Scratch (allocation-free: device globals)
__device__ float g_encproj[Bb * Ss * Dd];   // 33.5 MB
__device__ float g_context[Bb * Tt * Ee];   // 16.8 MB
__device__ int   g_lengths[Bb];

// ---------------------------------------------------------------------------
// Mask prologue: src_mask is a prefix mask (B,S) of bool. The harness may ship
// it as uint8 (numpy bool) or int32. Discriminate: int32 0/1 little-endian has
// every byte at offset%4!=0 equal to 0; a uint8 prefix mask (random lengths,
// fixed seed) has 1-bytes at such offsets. Then reduce to lengths[b].
// ---------------------------------------------------------------------------
__global__ void detect_lengths_kernel(const unsigned char* __restrict__ mask)
{
    __shared__ int s_flag;
    __shared__ int s_cnt[Bb];
    int tid = threadIdx.x;
    if (tid == 0) s_flag = 0;
    if (tid < Bb) s_cnt[tid] = 0;
    __syncthreads();

    int local = 0;
    for (int i = tid; i < Bb * Ss; i += 256)
        if ((i & 3) != 0 && mask[i] != 0) local = 1;
    if (local) atomicOr(&s_flag, 1);
    __syncthreads();

    bool isU8 = (s_flag != 0);
    int row = tid >> 4, part = tid & 15;
    int cnt = 0;
    if (isU8) {
        const unsigned char* p = mask + row * Ss + part * 128;
        #pragma unroll 4
        for (int e = 0; e < 128; e++) cnt += (p[e] != 0);
    } else {
        const int* p = ((const int*)mask) + row * Ss + part * 128;
        #pragma unroll 4
        for (int e = 0; e < 128; e++) cnt += (p[e] != 0);
    }
    atomicAdd(&s_cnt[row], cnt);
    __syncthreads();
    if (tid < Bb) g_lengths[tid] = s_cnt[tid];
}

// ---------------------------------------------------------------------------
// fp32 SGEMM, 128x128 block tile, 256 threads, 8x8 microtile, K-chunk 16.
// A row stride is always 256. SPLIT: A columns [0,256) from A1, [256,512) from
// A2 (virtual concat). TANH: fused tanh epilogue.
// ---------------------------------------------------------------------------
template<int K, bool SPLIT, bool TANH>
__global__ __launch_bounds__(256, 2)
void sgemm128_kernel(const float* __restrict__ A1, const float* __restrict__ A2,
                     const float* __restrict__ Bm, float* __restrict__ C, int N)
{
    __shared__ float As[16][132];  // A transposed: As[kk][m]
    __shared__ float Bs[16][128];

    int tid = threadIdx.x;
    int tx = tid & 15, ty = tid >> 4;
    int m0 = blockIdx.y * 128;
    int n0 = blockIdx.x * 128;

    float acc[8][8];
    #pragma unroll
    for (int i = 0; i < 8; i++)
        #pragma unroll
        for (int j = 0; j < 8; j++) acc[i][j] = 0.f;

    for (int k0 = 0; k0 < K; k0 += 16) {
        const float* Asrc;
        int kc;
        if (SPLIT && k0 >= 256) { Asrc = A2; kc = k0 - 256; }
        else                    { Asrc = A1; kc = k0; }

        #pragma unroll
        for (int u = 0; u < 2; u++) {
            int f = tid + u * 256;
            int row = f >> 2, c4 = f & 3;
            float4 v = *(const float4*)&Asrc[(size_t)(m0 + row) * 256 + kc + c4 * 4];
            As[c4 * 4 + 0][row] = v.x;
            As[c4 * 4 + 1][row] = v.y;
            As[c4 * 4 + 2][row] = v.z;
            As[c4 * 4 + 3][row] = v.w;
        }
        #pragma unroll
        for (int u = 0; u < 2; u++) {
            int f = tid + u * 256;
            int kr = f >> 5, c = f & 31;
            float4 v = *(const float4*)&Bm[(size_t)(k0 + kr) * N + n0 + c * 4];
            *(float4*)&Bs[kr][c * 4] = v;
        }
        __syncthreads();

        #pragma unroll
        for (int kk = 0; kk < 16; kk++) {
            float4 a0 = *(const float4*)&As[kk][ty * 8];
            float4 a1 = *(const float4*)&As[kk][ty * 8 + 4];
            float4 b0 = *(const float4*)&Bs[kk][tx * 8];
            float4 b1 = *(const float4*)&Bs[kk][tx * 8 + 4];
            float a[8] = {a0.x, a0.y, a0.z, a0.w, a1.x, a1.y, a1.z, a1.w};
            float b[8] = {b0.x, b0.y, b0.z, b0.w, b1.x, b1.y, b1.z, b1.w};
            #pragma unroll
            for (int i = 0; i < 8; i++)
                #pragma unroll
                for (int j = 0; j < 8; j++)
                    acc[i][j] += a[i] * b[j];
        }
        __syncthreads();
    }

    #pragma unroll
    for (int i = 0; i < 8; i++) {
        int row = m0 + ty * 8 + i;
        #pragma unroll
        for (int jv = 0; jv < 2; jv++) {
            float4 v;
            v.x = acc[i][jv * 4 + 0];
            v.y = acc[i][jv * 4 + 1];
            v.z = acc[i][jv * 4 + 2];
            v.w = acc[i][jv * 4 + 3];
            if (TANH) { v.x = tanhf(v.x); v.y = tanhf(v.y); v.z = tanhf(v.z); v.w = tanhf(v.w); }
            *(float4*)&C[(size_t)row * N + n0 + tx * 8 + jv * 4] = v;
        }
    }
}

// ---------------------------------------------------------------------------
// Fused flash attention: per block, 64 T-rows of one batch. Loop S in tiles of
// 64: scores = dec@encprojT (fp32), masked online softmax, context += p @ enc.
// 16x16 threads, 4x4 microtiles; context accumulator: 4 rows x 256 cols spread
// as ctx[i][chunk][j] (64 regs/thread).
// ---------------------------------------------------------------------------
__global__ __launch_bounds__(256, 2)
void attn_kernel(const float* __restrict__ dec, const float* __restrict__ enc)
{
    __shared__ float sDecT[16][64];     // dec chunk, transposed [k][t]
    __shared__ float sPT[16][64];       // encproj chunk, transposed [k][s]
    __shared__ float sS[64][68];        // scores [t][s], then p transposed [s][t]
    __shared__ float sEncC[64][68];     // enc 64x64 chunk [s][e]
    __shared__ float m_state[64], l_state[64], scaleArr[64];

    int tid = threadIdx.x;
    int tx = tid & 15, ty = tid >> 4;
    int b = blockIdx.y;
    int t0 = blockIdx.x * 64;
    int len = g_lengths[b];

    const float* decBase = dec + ((size_t)b * Tt + t0) * Dd;
    const float* encB = enc + (size_t)b * Ss * Ee;
    const float* projB = g_encproj + (size_t)b * Ss * Dd;

    if (tid < 64) { m_state[tid] = -1e30f; l_state[tid] = 0.f; }

    float ctx[4][4][4];  // [i (t-row)][chunk (e/64)][j (e-col)]
    #pragma unroll
    for (int i = 0; i < 4; i++)
        #pragma unroll
        for (int ch = 0; ch < 4; ch++)
            #pragma unroll
            for (int j = 0; j < 4; j++) ctx[i][ch][j] = 0.f;
    __syncthreads();

    int rowL = tid >> 2, l4 = tid & 3;  // softmax mapping: 4 lanes per row

    for (int s0 = 0; s0 < Ss; s0 += 64) {
        // ----- score GEMM: acc[i][j] = dec[t0+ty*4+i,:] . encproj[s0+tx*4+j,:]
        float acc[4][4];
        #pragma unroll
        for (int i = 0; i < 4; i++)
            #pragma unroll
            for (int j = 0; j < 4; j++) acc[i][j] = 0.f;

        for (int k0 = 0; k0 < 256; k0 += 16) {
            int lr = tid >> 2, c4 = tid & 3;
            float4 dv = *(const float4*)&decBase[(size_t)lr * Dd + k0 + c4 * 4];
            float4 pv = *(const float4*)&projB[(size_t)(s0 + lr) * Dd + k0 + c4 * 4];
            sDecT[c4 * 4 + 0][lr] = dv.x; sDecT[c4 * 4 + 1][lr] = dv.y;
            sDecT[c4 * 4 + 2][lr] = dv.z; sDecT[c4 * 4 + 3][lr] = dv.w;
            sPT[c4 * 4 + 0][lr] = pv.x;  sPT[c4 * 4 + 1][lr] = pv.y;
            sPT[c4 * 4 + 2][lr] = pv.z;  sPT[c4 * 4 + 3][lr] = pv.w;
            __syncthreads();
            #pragma unroll
            for (int kk = 0; kk < 16; kk++) {
                float4 av = *(const float4*)&sDecT[kk][ty * 4];
                float4 cv = *(const float4*)&sPT[kk][tx * 4];
                float a[4] = {av.x, av.y, av.z, av.w};
                float c[4] = {cv.x, cv.y, cv.z, cv.w};
                #pragma unroll
                for (int i = 0; i < 4; i++)
                    #pragma unroll
                    for (int j = 0; j < 4; j++)
                        acc[i][j] += a[i] * c[j];
            }
            __syncthreads();
        }

        // ----- write masked scores
        #pragma unroll
        for (int j = 0; j < 4; j++) {
            bool valid = (s0 + tx * 4 + j) < len;
            #pragma unroll
            for (int i = 0; i < 4; i++)
                sS[ty * 4 + i][tx * 4 + j] = valid ? acc[i][j] : -1e30f;
        }
        __syncthreads();

        // ----- online softmax (4 lanes per row, 16 cols each)
        float v[16];
        float tmax = -1e30f;
        #pragma unroll
        for (int q = 0; q < 16; q++) {
            v[q] = sS[rowL][l4 * 16 + q];
            tmax = fmaxf(tmax, v[q]);
        }
        tmax = fmaxf(tmax, __shfl_xor_sync(0xffffffffu, tmax, 1));
        tmax = fmaxf(tmax, __shfl_xor_sync(0xffffffffu, tmax, 2));
        float mOld = m_state[rowL];
        float mNew = fmaxf(mOld, tmax);
        float sum = 0.f;
        #pragma unroll
        for (int q = 0; q < 16; q++) {
            v[q] = expf(v[q] - mNew);
            sum += v[q];
        }
        sum += __shfl_xor_sync(0xffffffffu, sum, 1);
        sum += __shfl_xor_sync(0xffffffffu, sum, 2);
        float scl = expf(mOld - mNew);
        __syncwarp();
        if (l4 == 0) {
            m_state[rowL] = mNew;
            l_state[rowL] = l_state[rowL] * scl + sum;
            scaleArr[rowL] = scl;
        }
        __syncthreads();  // reads of sS done; states/scaleArr visible

        // ----- write p transposed: sS[s][t]
        #pragma unroll
        for (int q = 0; q < 16; q++) sS[l4 * 16 + q][rowL] = v[q];

        // rescale context accumulators
        float ms[4];
        #pragma unroll
        for (int i = 0; i < 4; i++) ms[i] = scaleArr[ty * 4 + i];
        #pragma unroll
        for (int i = 0; i < 4; i++)
            #pragma unroll
            for (int ch = 0; ch < 4; ch++)
                #pragma unroll
                for (int j = 0; j < 4; j++) ctx[i][ch][j] *= ms[i];
        __syncthreads();  // transpose complete

        // ----- context GEMM: ctx[t][e] += sum_s p[t][s] * enc[s][e]
        #pragma unroll
        for (int ch = 0; ch < 4; ch++) {
            #pragma unroll
            for (int u = 0; u < 4; u++) {
                int f = tid + u * 256;
                int lr = f >> 4, c4 = f & 15;
                float4 ev = *(const float4*)&encB[(size_t)(s0 + lr) * Ee + ch * 64 + c4 * 4];
                *(float4*)&sEncC[lr][c4 * 4] = ev;
            }
            __syncthreads();
            #pragma unroll 8
            for (int s = 0; s < 64; s++) {
                float4 wf = *(const float4*)&sS[s][ty * 4];
                float4 ef = *(const float4*)&sEncC[s][tx * 4];
                float w[4] = {wf.x, wf.y, wf.z, wf.w};
                float e[4] = {ef.x, ef.y, ef.z, ef.w};
                #pragma unroll
                for (int i = 0; i < 4; i++)
                    #pragma unroll
                    for (int j = 0; j < 4; j++)
                        ctx[i][ch][j] += w[i] * e[j];
            }
            __syncthreads();
        }
    }

    // ----- normalize + write context
    #pragma unroll
    for (int i = 0; i < 4; i++) {
        float inv = 1.0f / l_state[ty * 4 + i];
        int row = t0 + ty * 4 + i;
        float* outp = g_context + ((size_t)b * Tt + row) * Ee;
        #pragma unroll
        for (int ch = 0; ch < 4; ch++) {
            float4 o;
            o.x = ctx[i][ch][0] * inv;
            o.y = ctx[i][ch][1] * inv;
            o.z = ctx[i][ch][2] * inv;
            o.w = ctx[i][ch][3] * inv;
            *(float4*)&outp[ch * 64 + tx * 4] = o;
        }
    }
}

// ---------------------------------------------------------------------------
extern "C" void kernel_launch(void* const* d_in, const int* in_sizes, int n_in,
                              void* d_out, int out_size)
{
    (void)in_sizes; (void)n_in; (void)out_size;
    const float* enc = (const float*)d_in[0];
    const float* dec = (const float*)d_in[1];
    const unsigned char* mask = (const unsigned char*)d_in[2];
    const float* W_enc = (const float*)d_in[3];
    const float* W_fin = (const float*)d_in[4];
    float* out = (float*)d_out;

    void* p_encproj = nullptr;
    void* p_context = nullptr;
    cudaGetSymbolAddress(&p_encproj, g_encproj);
    cudaGetSymbolAddress(&p_context, g_context);

    detect_lengths_kernel<<<1, 256>>>(mask);

    dim3 g1(2, 256);  // N=256 -> 2 tiles, M=32768 -> 256 tiles
    sgemm128_kernel<256, false, false><<<g1, 256>>>(enc, nullptr, W_enc,
                                                    (float*)p_encproj, 256);

    dim3 g2(Tt / 64, Bb);  // (16, 16)
    attn_kernel<<<g2, 256>>>(dec, enc);

    dim3 g3(2, 128);  // M=16384 -> 128 tiles
    sgemm128_kernel<512, true, true><<<g3, 256>>>((const float*)p_context, dec,
                                                  W_fin, out, 256);
}

// round 3
// speedup vs baseline: 2.9083x; 2.9083x over previous
#include <cuda_runtime.h>
#include <cuda_bf16.h>
#include <math.h>
#include <stdint.h>

#define Bb 16
#define Ss 2048
#define Tt 1024
#define Ee 256
#define Dd 256

// ---------------------------------------------------------------------------
// Scratch (allocation-free: device globals). bf16 hi/lo split representations.
// ---------------------------------------------------------------------------
__device__ __nv_bfloat16 g_encH[Bb * Ss * Ee];
__device__ __nv_bfloat16 g_encL[Bb * Ss * Ee];
__device__ __nv_bfloat16 g_decH[Bb * Tt * Dd];
__device__ __nv_bfloat16 g_decL[Bb * Tt * Dd];
__device__ __nv_bfloat16 g_projH[Bb * Ss * Dd];
__device__ __nv_bfloat16 g_projL[Bb * Ss * Dd];
__device__ __nv_bfloat16 g_ctxH[Bb * Tt * Ee];
__device__ __nv_bfloat16 g_ctxL[Bb * Tt * Ee];
__device__ __nv_bfloat16 g_WencTH[Dd * Ee];      // [d][e]
__device__ __nv_bfloat16 g_WencTL[Dd * Ee];
__device__ __nv_bfloat16 g_WfinTH[Dd * (Ee + Dd)];  // [d][f], f = 512
__device__ __nv_bfloat16 g_WfinTL[Dd * (Ee + Dd)];
__device__ int g_lengths[Bb];

// ---------------------------------------------------------------------------
// Helpers
// ---------------------------------------------------------------------------
__device__ __forceinline__ uint32_t smem_u32(const void* p) {
    uint32_t a;
    asm("{ .reg .u64 t; cvta.to.shared.u64 t, %1; cvt.u32.u64 %0, t; }"
        : "=r"(a) : "l"(p));
    return a;
}

__device__ __forceinline__ void mma16816(float* d, const uint32_t* a,
                                         const uint32_t* b) {
    asm volatile(
        "mma.sync.aligned.m16n8k16.row.col.f32.bf16.bf16.f32 "
        "{%0,%1,%2,%3}, {%4,%5,%6,%7}, {%8,%9}, {%0,%1,%2,%3};"
        : "+f"(d[0]), "+f"(d[1]), "+f"(d[2]), "+f"(d[3])
        : "r"(a[0]), "r"(a[1]), "r"(a[2]), "r"(a[3]), "r"(b[0]), "r"(b[1]));
}

__device__ __forceinline__ void ldsm_x4_t(uint32_t& r0, uint32_t& r1,
                                          uint32_t& r2, uint32_t& r3,
                                          uint32_t addr) {
    asm volatile("ldmatrix.sync.aligned.m8n8.x4.trans.shared.b16 "
                 "{%0,%1,%2,%3}, [%4];"
                 : "=r"(r0), "=r"(r1), "=r"(r2), "=r"(r3) : "r"(addr));
}

__device__ __forceinline__ void bsplit(float x, unsigned short& h,
                                       unsigned short& l) {
    __nv_bfloat16 hb = __float2bfloat16(x);
    __nv_bfloat16 lb = __float2bfloat16(x - __bfloat162float(hb));
    h = *(unsigned short*)&hb;
    l = *(unsigned short*)&lb;
}

__device__ __forceinline__ uint32_t pack2(unsigned short a, unsigned short b) {
    return (uint32_t)a | ((uint32_t)b << 16);
}

// ---------------------------------------------------------------------------
// Mask prologue (unchanged; handles uint8 or int32 bool encodings)
// ---------------------------------------------------------------------------
__global__ void detect_lengths_kernel(const unsigned char* __restrict__ mask)
{
    __shared__ int s_flag;
    __shared__ int s_cnt[Bb];
    int tid = threadIdx.x;
    if (tid == 0) s_flag = 0;
    if (tid < Bb) s_cnt[tid] = 0;
    __syncthreads();

    int local = 0;
    for (int i = tid; i < Bb * Ss; i += 256)
        if ((i & 3) != 0 && mask[i] != 0) local = 1;
    if (local) atomicOr(&s_flag, 1);
    __syncthreads();

    bool isU8 = (s_flag != 0);
    int row = tid >> 4, part = tid & 15;
    int cnt = 0;
    if (isU8) {
        const unsigned char* p = mask + row * Ss + part * 128;
        #pragma unroll 4
        for (int e = 0; e < 128; e++) cnt += (p[e] != 0);
    } else {
        const int* p = ((const int*)mask) + row * Ss + part * 128;
        #pragma unroll 4
        for (int e = 0; e < 128; e++) cnt += (p[e] != 0);
    }
    atomicAdd(&s_cnt[row], cnt);
    __syncthreads();
    if (tid < Bb) g_lengths[tid] = s_cnt[tid];
}

// ---------------------------------------------------------------------------
// Prep: fp32 -> bf16 hi/lo for enc, dec; transposed hi/lo for weights.
// ---------------------------------------------------------------------------
__global__ void prep_convert_kernel(const float* __restrict__ enc,
                                    const float* __restrict__ dec,
                                    const float* __restrict__ Wenc,
                                    const float* __restrict__ Wfin)
{
    int tid = blockIdx.x * blockDim.x + threadIdx.x;
    int stride = gridDim.x * blockDim.x;

    const int NE4 = (Bb * Ss * Ee) / 4;
    for (int i = tid; i < NE4; i += stride) {
        float4 v = ((const float4*)enc)[i];
        ushort4 hv, lv;
        bsplit(v.x, hv.x, lv.x); bsplit(v.y, hv.y, lv.y);
        bsplit(v.z, hv.z, lv.z); bsplit(v.w, hv.w, lv.w);
        ((ushort4*)g_encH)[i] = hv;
        ((ushort4*)g_encL)[i] = lv;
    }
    const int ND4 = (Bb * Tt * Dd) / 4;
    for (int i = tid; i < ND4; i += stride) {
        float4 v = ((const float4*)dec)[i];
        ushort4 hv, lv;
        bsplit(v.x, hv.x, lv.x); bsplit(v.y, hv.y, lv.y);
        bsplit(v.z, hv.z, lv.z); bsplit(v.w, hv.w, lv.w);
        ((ushort4*)g_decH)[i] = hv;
        ((ushort4*)g_decL)[i] = lv;
    }
    for (int i = tid; i < 256 * 256; i += stride) {
        int d = i >> 8, e = i & 255;
        unsigned short h, l;
        bsplit(Wenc[e * 256 + d], h, l);
        *(unsigned short*)&g_WencTH[i] = h;
        *(unsigned short*)&g_WencTL[i] = l;
    }
    for (int i = tid; i < 256 * 512; i += stride) {
        int d = i >> 9, f = i & 511;
        unsigned short h, l;
        bsplit(Wfin[f * 256 + d], h, l);
        *(unsigned short*)&g_WfinTH[i] = h;
        *(unsigned short*)&g_WfinTL[i] = l;
    }
}

// ---------------------------------------------------------------------------
// Split-bf16 tensor-core GEMM: C[M x 256] = A[M x KTOT] @ B[KTOT x 256]
// A given as hi/lo row-major [m][256] (two source regions when KTOT=512:
// k<256 from A1 (ctx), k>=256 from A2 (dec)). B given transposed hi/lo
// [n][KTOT] (k contiguous). 128x128 block, 8 warps (4m x 2n), warp 32x64.
// TANH: fp32 tanh output; else bf16 hi/lo split output (proj).
// ---------------------------------------------------------------------------
#define GSM_A_H 0
#define GSM_A_L 18432
#define GSM_B_H 36864
#define GSM_B_L 55296
#define GSM_TOTAL 73728   // 4 x 128 x 72 x 2B

template<int KTOT, bool TANH>
__global__ __launch_bounds__(256, 2)
void mma_gemm_kernel(const __nv_bfloat16* __restrict__ A1H,
                     const __nv_bfloat16* __restrict__ A1L,
                     const __nv_bfloat16* __restrict__ A2H,
                     const __nv_bfloat16* __restrict__ A2L,
                     const __nv_bfloat16* __restrict__ BTH,
                     const __nv_bfloat16* __restrict__ BTL,
                     float* __restrict__ Cf,
                     __nv_bfloat16* __restrict__ CH,
                     __nv_bfloat16* __restrict__ CL)
{
    extern __shared__ char dyn[];
    __nv_bfloat16* sAH = (__nv_bfloat16*)(dyn + GSM_A_H);
    __nv_bfloat16* sAL = (__nv_bfloat16*)(dyn + GSM_A_L);
    __nv_bfloat16* sBH = (__nv_bfloat16*)(dyn + GSM_B_H);
    __nv_bfloat16* sBL = (__nv_bfloat16*)(dyn + GSM_B_L);

    int tid = threadIdx.x, lane = tid & 31, wid = tid >> 5;
    int warpM = wid & 3, warpN = wid >> 2;
    int m0 = blockIdx.y * 128, n0 = blockIdx.x * 128;
    int r = lane >> 2, cc = (lane & 3) * 2;

    float acc[2][8][4];
    #pragma unroll
    for (int i = 0; i < 2; i++)
        #pragma unroll
        for (int j = 0; j < 8; j++)
            #pragma unroll
            for (int q = 0; q < 4; q++) acc[i][j][q] = 0.f;

    for (int kc = 0; kc < KTOT; kc += 64) {
        const __nv_bfloat16* AH = A1H;
        const __nv_bfloat16* AL = A1L;
        int kcol = kc;
        if (KTOT > 256 && kc >= 256) { AH = A2H; AL = A2L; kcol = kc - 256; }

        #pragma unroll
        for (int u = 0; u < 4; u++) {
            int f = tid + u * 256;
            int rr = f >> 3, c8 = f & 7;
            *(uint4*)&sAH[rr * 72 + c8 * 8] =
                *(const uint4*)&AH[(size_t)(m0 + rr) * 256 + kcol + c8 * 8];
            *(uint4*)&sAL[rr * 72 + c8 * 8] =
                *(const uint4*)&AL[(size_t)(m0 + rr) * 256 + kcol + c8 * 8];
            *(uint4*)&sBH[rr * 72 + c8 * 8] =
                *(const uint4*)&BTH[(size_t)(n0 + rr) * KTOT + kc + c8 * 8];
            *(uint4*)&sBL[rr * 72 + c8 * 8] =
                *(const uint4*)&BTL[(size_t)(n0 + rr) * KTOT + kc + c8 * 8];
        }
        __syncthreads();

        #pragma unroll
        for (int ks = 0; ks < 4; ks++) {
            int k0 = ks * 16;
            uint32_t aH[2][4], aL[2][4];
            #pragma unroll
            for (int mt = 0; mt < 2; mt++) {
                int ar = warpM * 32 + mt * 16 + r;
                int ac = k0 + cc;
                aH[mt][0] = *(uint32_t*)&sAH[ar * 72 + ac];
                aH[mt][1] = *(uint32_t*)&sAH[(ar + 8) * 72 + ac];
                aH[mt][2] = *(uint32_t*)&sAH[ar * 72 + ac + 8];
                aH[mt][3] = *(uint32_t*)&sAH[(ar + 8) * 72 + ac + 8];
                aL[mt][0] = *(uint32_t*)&sAL[ar * 72 + ac];
                aL[mt][1] = *(uint32_t*)&sAL[(ar + 8) * 72 + ac];
                aL[mt][2] = *(uint32_t*)&sAL[ar * 72 + ac + 8];
                aL[mt][3] = *(uint32_t*)&sAL[(ar + 8) * 72 + ac + 8];
            }
            #pragma unroll
            for (int nt = 0; nt < 8; nt++) {
                int bn = warpN * 64 + nt * 8 + r;
                int bc = k0 + cc;
                uint32_t bH[2], bL[2];
                bH[0] = *(uint32_t*)&sBH[bn * 72 + bc];
                bH[1] = *(uint32_t*)&sBH[bn * 72 + bc + 8];
                bL[0] = *(uint32_t*)&sBL[bn * 72 + bc];
                bL[1] = *(uint32_t*)&sBL[bn * 72 + bc + 8];
                #pragma unroll
                for (int mt = 0; mt < 2; mt++) {
                    mma16816(acc[mt][nt], aH[mt], bH);
                    mma16816(acc[mt][nt], aH[mt], bL);
                    mma16816(acc[mt][nt], aL[mt], bH);
                }
            }
        }
        __syncthreads();
    }

    // Epilogue
    #pragma unroll
    for (int mt = 0; mt < 2; mt++) {
        #pragma unroll
        for (int nt = 0; nt < 8; nt++) {
            int m = m0 + warpM * 32 + mt * 16 + r;
            int n = n0 + warpN * 64 + nt * 8 + cc;
            float c0 = acc[mt][nt][0], c1 = acc[mt][nt][1];
            float c2 = acc[mt][nt][2], c3 = acc[mt][nt][3];
            if (TANH) {
                float2 v0 = make_float2(tanhf(c0), tanhf(c1));
                float2 v1 = make_float2(tanhf(c2), tanhf(c3));
                *(float2*)&Cf[(size_t)m * 256 + n] = v0;
                *(float2*)&Cf[(size_t)(m + 8) * 256 + n] = v1;
            } else {
                unsigned short h0, l0, h1, l1, h2, l2, h3, l3;
                bsplit(c0, h0, l0); bsplit(c1, h1, l1);
                bsplit(c2, h2, l2); bsplit(c3, h3, l3);
                *(uint32_t*)&CH[(size_t)m * 256 + n] = pack2(h0, h1);
                *(uint32_t*)&CL[(size_t)m * 256 + n] = pack2(l0, l1);
                *(uint32_t*)&CH[(size_t)(m + 8) * 256 + n] = pack2(h2, h3);
                *(uint32_t*)&CL[(size_t)(m + 8) * 256 + n] = pack2(l2, l3);
            }
        }
    }
}

// ---------------------------------------------------------------------------
// Fused flash attention, tensor-core split-bf16.
// Block: 64 T-rows of one batch, 256 thr (8 warps). S tiled by 64 up to len.
// Scores: warps 4t x 2s; Context: warps 4t x 2e (per 128-e chunk).
// ---------------------------------------------------------------------------
#define ASM_A_H   0        // 64 x 72 bf16: dec chunk hi, reused as p hi
#define ASM_A_L   9216
#define ASM_B_H   18432    // proj chunk hi
#define ASM_B_L   27648
#define ASM_S     36864    // 64 x 68 fp32 scores
#define ASM_ENC_H 54272    // 64 x 136 bf16 enc chunk hi
#define ASM_ENC_L 71680
#define ASM_M     89088    // 64 fp32
#define ASM_L     89344
#define ASM_SC    89600
#define ASM_TOTAL 89856

__global__ __launch_bounds__(256, 2)
void attn_kernel()
{
    extern __shared__ char dyn[];
    __nv_bfloat16* sAH = (__nv_bfloat16*)(dyn + ASM_A_H);
    __nv_bfloat16* sAL = (__nv_bfloat16*)(dyn + ASM_A_L);
    __nv_bfloat16* sBH = (__nv_bfloat16*)(dyn + ASM_B_H);
    __nv_bfloat16* sBL = (__nv_bfloat16*)(dyn + ASM_B_L);
    float* sS = (float*)(dyn + ASM_S);
    __nv_bfloat16* sEH = (__nv_bfloat16*)(dyn + ASM_ENC_H);
    __nv_bfloat16* sEL = (__nv_bfloat16*)(dyn + ASM_ENC_L);
    float* mstat = (float*)(dyn + ASM_M);
    float* lstat = (float*)(dyn + ASM_L);
    float* sscale = (float*)(dyn + ASM_SC);

    uint32_t encHb = smem_u32(dyn) + ASM_ENC_H;
    uint32_t encLb = smem_u32(dyn) + ASM_ENC_L;

    int tid = threadIdx.x, lane = tid & 31, wid = tid >> 5;
    int warpT = wid & 3;      // 16 t-rows per warp group
    int warpS = wid >> 2;     // score phase: 32 s-cols half
    int r = lane >> 2, cc = (lane & 3) * 2;
    int b = blockIdx.y;
    int t0 = blockIdx.x * 64;
    int len = g_lengths[b];

    if (tid < 64) { mstat[tid] = -1e30f; lstat[tid] = 0.f; }

    float ctx[2][8][4];
    #pragma unroll
    for (int i = 0; i < 2; i++)
        #pragma unroll
        for (int j = 0; j < 8; j++)
            #pragma unroll
            for (int q = 0; q < 4; q++) ctx[i][j][q] = 0.f;
    __syncthreads();

    int rowL = tid >> 2, l4 = tid & 3;
    size_t decBase = ((size_t)b * Tt + t0) * 256;
    size_t encBase = (size_t)b * Ss * 256;

    int nst = (len + 63) >> 6;
    for (int st = 0; st < nst; st++) {
        int s0 = st * 64;

        // ---------------- score GEMM: 64t x 64s, K=256 in 4 chunks ---------
        float sacc[4][4];
        #pragma unroll
        for (int j = 0; j < 4; j++)
            #pragma unroll
            for (int q = 0; q < 4; q++) sacc[j][q] = 0.f;

        for (int kcч = 0; kcч < 4; kcч++) {
            int kc = kcч * 64;
            #pragma unroll
            for (int u = 0; u < 2; u++) {
                int f = tid + u * 256;
                int rr = f >> 3, c8 = f & 7;
                *(uint4*)&sAH[rr * 72 + c8 * 8] =
                    *(const uint4*)&g_decH[decBase + (size_t)rr * 256 + kc + c8 * 8];
                *(uint4*)&sAL[rr * 72 + c8 * 8] =
                    *(const uint4*)&g_decL[decBase + (size_t)rr * 256 + kc + c8 * 8];
                *(uint4*)&sBH[rr * 72 + c8 * 8] =
                    *(const uint4*)&g_projH[encBase + (size_t)(s0 + rr) * 256 + kc + c8 * 8];
                *(uint4*)&sBL[rr * 72 + c8 * 8] =
                    *(const uint4*)&g_projL[encBase + (size_t)(s0 + rr) * 256 + kc + c8 * 8];
            }
            __syncthreads();

            #pragma unroll
            for (int ks = 0; ks < 4; ks++) {
                int k0 = ks * 16;
                int ar = warpT * 16 + r;
                int ac = k0 + cc;
                uint32_t aH[4], aL[4];
                aH[0] = *(uint32_t*)&sAH[ar * 72 + ac];
                aH[1] = *(uint32_t*)&sAH[(ar + 8) * 72 + ac];
                aH[2] = *(uint32_t*)&sAH[ar * 72 + ac + 8];
                aH[3] = *(uint32_t*)&sAH[(ar + 8) * 72 + ac + 8];
                aL[0] = *(uint32_t*)&sAL[ar * 72 + ac];
                aL[1] = *(uint32_t*)&sAL[(ar + 8) * 72 + ac];
                aL[2] = *(uint32_t*)&sAL[ar * 72 + ac + 8];
                aL[3] = *(uint32_t*)&sAL[(ar + 8) * 72 + ac + 8];
                #pragma unroll
                for (int nt = 0; nt < 4; nt++) {
                    int bn = warpS * 32 + nt * 8 + r;
                    uint32_t bH[2], bL[2];
                    bH[0] = *(uint32_t*)&sBH[bn * 72 + ac];
                    bH[1] = *(uint32_t*)&sBH[bn * 72 + ac + 8];
                    bL[0] = *(uint32_t*)&sBL[bn * 72 + ac];
                    bL[1] = *(uint32_t*)&sBL[bn * 72 + ac + 8];
                    mma16816(sacc[nt], aH, bH);
                    mma16816(sacc[nt], aH, bL);
                    mma16816(sacc[nt], aL, bH);
                }
            }
            __syncthreads();
        }

        // write scores to smem
        #pragma unroll
        for (int nt = 0; nt < 4; nt++) {
            int tr = warpT * 16 + r;
            int sc = warpS * 32 + nt * 8 + cc;
            *(float2*)&sS[tr * 68 + sc] = make_float2(sacc[nt][0], sacc[nt][1]);
            *(float2*)&sS[(tr + 8) * 68 + sc] = make_float2(sacc[nt][2], sacc[nt][3]);
        }
        __syncthreads();

        // ---------------- online softmax (4 lanes per row) -----------------
        float v[16];
        float tmax = -1e30f;
        int sbase = l4 * 16;
        #pragma unroll
        for (int q = 0; q < 16; q++) {
            int sc = sbase + q;
            float val = (s0 + sc < len) ? sS[rowL * 68 + sc] : -1e30f;
            v[q] = val;
            tmax = fmaxf(tmax, val);
        }
        tmax = fmaxf(tmax, __shfl_xor_sync(0xffffffffu, tmax, 1));
        tmax = fmaxf(tmax, __shfl_xor_sync(0xffffffffu, tmax, 2));
        float mOld = mstat[rowL];
        float mNew = fmaxf(mOld, tmax);
        float sum = 0.f;
        #pragma unroll
        for (int q = 0; q < 16; q++) {
            v[q] = __expf(v[q] - mNew);
            sum += v[q];
        }
        sum += __shfl_xor_sync(0xffffffffu, sum, 1);
        sum += __shfl_xor_sync(0xffffffffu, sum, 2);
        float scl = __expf(mOld - mNew);
        if (l4 == 0) {
            mstat[rowL] = mNew;
            lstat[rowL] = lstat[rowL] * scl + sum;
            sscale[rowL] = scl;
        }
        // write p hi/lo into sAH/sAL (dec chunk regions, dead now)
        #pragma unroll
        for (int q = 0; q < 16; q++) {
            unsigned short h, l;
            bsplit(v[q], h, l);
            *(unsigned short*)&sAH[rowL * 72 + sbase + q] = h;
            *(unsigned short*)&sAL[rowL * 72 + sbase + q] = l;
        }
        __syncthreads();

        // rescale context accumulators
        float f0 = sscale[warpT * 16 + r];
        float f1 = sscale[warpT * 16 + r + 8];
        #pragma unroll
        for (int i = 0; i < 2; i++)
            #pragma unroll
            for (int j = 0; j < 8; j++) {
                ctx[i][j][0] *= f0; ctx[i][j][1] *= f0;
                ctx[i][j][2] *= f1; ctx[i][j][3] *= f1;
            }

        // ---------------- context GEMM: ctx += p @ enc ---------------------
        #pragma unroll
        for (int ec = 0; ec < 2; ec++) {
            #pragma unroll
            for (int u = 0; u < 4; u++) {
                int f = tid + u * 256;
                int rr = f >> 4, c8 = f & 15;
                *(uint4*)&sEH[rr * 136 + c8 * 8] =
                    *(const uint4*)&g_encH[encBase + (size_t)(s0 + rr) * 256 + ec * 128 + c8 * 8];
                *(uint4*)&sEL[rr * 136 + c8 * 8] =
                    *(const uint4*)&g_encL[encBase + (size_t)(s0 + rr) * 256 + ec * 128 + c8 * 8];
            }
            __syncthreads();

            #pragma unroll
            for (int ks = 0; ks < 4; ks++) {
                int k0 = ks * 16;
                int ar = warpT * 16 + r;
                int ac = k0 + cc;
                uint32_t aH[4], aL[4];
                aH[0] = *(uint32_t*)&sAH[ar * 72 + ac];
                aH[1] = *(uint32_t*)&sAH[(ar + 8) * 72 + ac];
                aH[2] = *(uint32_t*)&sAH[ar * 72 + ac + 8];
                aH[3] = *(uint32_t*)&sAH[(ar + 8) * 72 + ac + 8];
                aL[0] = *(uint32_t*)&sAL[ar * 72 + ac];
                aL[1] = *(uint32_t*)&sAL[(ar + 8) * 72 + ac];
                aL[2] = *(uint32_t*)&sAL[ar * 72 + ac + 8];
                aL[3] = *(uint32_t*)&sAL[(ar + 8) * 72 + ac + 8];
                // enc B-frags via ldmatrix.trans: row = k0 + (lane&15),
                // col = warpS*64 + pair*16 + ((lane>>4)<<3)
                uint32_t lrow = (uint32_t)(k0 + (lane & 15));
                uint32_t lcol0 = (uint32_t)(warpS * 64 + ((lane >> 4) << 3));
                #pragma unroll
                for (int pair = 0; pair < 4; pair++) {
                    uint32_t off = (lrow * 136 + lcol0 + pair * 16) * 2;
                    uint32_t bh0, bh1, bh2, bh3, bl0, bl1, bl2, bl3;
                    ldsm_x4_t(bh0, bh1, bh2, bh3, encHb + off);
                    ldsm_x4_t(bl0, bl1, bl2, bl3, encLb + off);
                    uint32_t bH0[2] = {bh0, bh1}, bH1[2] = {bh2, bh3};
                    uint32_t bL0[2] = {bl0, bl1}, bL1[2] = {bl2, bl3};
                    int nt = pair * 2;
                    mma16816(ctx[ec][nt], aH, bH0);
                    mma16816(ctx[ec][nt], aH, bL0);
                    mma16816(ctx[ec][nt], aL, bH0);
                    mma16816(ctx[ec][nt + 1], aH, bH1);
                    mma16816(ctx[ec][nt + 1], aH, bL1);
                    mma16816(ctx[ec][nt + 1], aL, bH1);
                }
            }
            __syncthreads();
        }
    }

    // ---------------- normalize + split-store context ----------------------
    float i0 = 1.0f / lstat[warpT * 16 + r];
    float i1 = 1.0f / lstat[warpT * 16 + r + 8];
    int t = t0 + warpT * 16 + r;
    size_t obase = ((size_t)b * Tt + t) * 256;
    #pragma unroll
    for (int ec = 0; ec < 2; ec++) {
        #pragma unroll
        for (int nt = 0; nt < 8; nt++) {
            int e = ec * 128 + warpS * 64 + nt * 8 + cc;
            unsigned short h0, l0, h1, l1, h2, l2, h3, l3;
            bsplit(ctx[ec][nt][0] * i0, h0, l0);
            bsplit(ctx[ec][nt][1] * i0, h1, l1);
            bsplit(ctx[ec][nt][2] * i1, h2, l2);
            bsplit(ctx[ec][nt][3] * i1, h3, l3);
            *(uint32_t*)&g_ctxH[obase + e] = pack2(h0, h1);
            *(uint32_t*)&g_ctxL[obase + e] = pack2(l0, l1);
            *(uint32_t*)&g_ctxH[obase + 8 * 256 + e] = pack2(h2, h3);
            *(uint32_t*)&g_ctxL[obase + 8 * 256 + e] = pack2(l2, l3);
        }
    }
}

// ---------------------------------------------------------------------------
extern "C" void kernel_launch(void* const* d_in, const int* in_sizes, int n_in,
                              void* d_out, int out_size)
{
    (void)in_sizes; (void)n_in; (void)out_size;
    const float* enc = (const float*)d_in[0];
    const float* dec = (const float*)d_in[1];
    const unsigned char* mask = (const unsigned char*)d_in[2];
    const float* W_enc = (const float*)d_in[3];
    const float* W_fin = (const float*)d_in[4];
    float* out = (float*)d_out;

    void *pEncH, *pEncL, *pDecH, *pDecL, *pProjH, *pProjL;
    void *pCtxH, *pCtxL, *pWeH, *pWeL, *pWfH, *pWfL;
    cudaGetSymbolAddress(&pEncH, g_encH);
    cudaGetSymbolAddress(&pEncL, g_encL);
    cudaGetSymbolAddress(&pDecH, g_decH);
    cudaGetSymbolAddress(&pDecL, g_decL);
    cudaGetSymbolAddress(&pProjH, g_projH);
    cudaGetSymbolAddress(&pProjL, g_projL);
    cudaGetSymbolAddress(&pCtxH, g_ctxH);
    cudaGetSymbolAddress(&pCtxL, g_ctxL);
    cudaGetSymbolAddress(&pWeH, g_WencTH);
    cudaGetSymbolAddress(&pWeL, g_WencTL);
    cudaGetSymbolAddress(&pWfH, g_WfinTH);
    cudaGetSymbolAddress(&pWfL, g_WfinTL);

    cudaFuncSetAttribute((const void*)mma_gemm_kernel<256, false>,
                         cudaFuncAttributeMaxDynamicSharedMemorySize, GSM_TOTAL);
    cudaFuncSetAttribute((const void*)mma_gemm_kernel<512, true>,
                         cudaFuncAttributeMaxDynamicSharedMemorySize, GSM_TOTAL);
    cudaFuncSetAttribute((const void*)attn_kernel,
                         cudaFuncAttributeMaxDynamicSharedMemorySize, ASM_TOTAL);

    detect_lengths_kernel<<<1, 256>>>(mask);
    prep_convert_kernel<<<1024, 256>>>(enc, dec, W_enc, W_fin);

    // GEMM1: proj = enc @ W_enc  -> bf16 hi/lo
    dim3 g1(2, 256);
    mma_gemm_kernel<256, false><<<g1, 256, GSM_TOTAL>>>(
        (const __nv_bfloat16*)pEncH, (const __nv_bfloat16*)pEncL,
        nullptr, nullptr,
        (const __nv_bfloat16*)pWeH, (const __nv_bfloat16*)pWeL,
        nullptr, (__nv_bfloat16*)pProjH, (__nv_bfloat16*)pProjL);

    dim3 g2(Tt / 64, Bb);
    attn_kernel<<<g2, 256, ASM_TOTAL>>>();

    // GEMM3: out = tanh([ctx | dec] @ W_fin)
    dim3 g3(2, 128);
    mma_gemm_kernel<512, true><<<g3, 256, GSM_TOTAL>>>(
        (const __nv_bfloat16*)pCtxH, (const __nv_bfloat16*)pCtxL,
        (const __nv_bfloat16*)pDecH, (const __nv_bfloat16*)pDecL,
        (const __nv_bfloat16*)pWfH, (const __nv_bfloat16*)pWfL,
        out, nullptr, nullptr);
}

// round 4
// speedup vs baseline: 3.6141x; 1.2427x over previous
#include <cuda_runtime.h>
#include <cuda_bf16.h>
#include <math.h>
#include <stdint.h>

#define Bb 16
#define Ss 2048
#define Tt 1024
#define Ee 256
#define Dd 256
#define NSLICE 4
#define SLICE_S 512

// ---------------------------------------------------------------------------
// Scratch (allocation-free: device globals). bf16 hi/lo split representations.
// ---------------------------------------------------------------------------
__device__ __nv_bfloat16 g_encH[Bb * Ss * Ee];
__device__ __nv_bfloat16 g_encL[Bb * Ss * Ee];
__device__ __nv_bfloat16 g_decH[Bb * Tt * Dd];
__device__ __nv_bfloat16 g_decL[Bb * Tt * Dd];
__device__ __nv_bfloat16 g_projH[Bb * Ss * Dd];
__device__ __nv_bfloat16 g_projL[Bb * Ss * Dd];
__device__ __nv_bfloat16 g_ctxH[Bb * Tt * Ee];
__device__ __nv_bfloat16 g_ctxL[Bb * Tt * Ee];
__device__ __nv_bfloat16 g_WencTH[Dd * Ee];      // [d][e]
__device__ __nv_bfloat16 g_WencTL[Dd * Ee];
__device__ __nv_bfloat16 g_WfinTH[Dd * (Ee + Dd)];  // [d][f], f = 512
__device__ __nv_bfloat16 g_WfinTL[Dd * (Ee + Dd)];
__device__ int g_lengths[Bb];
// split-KV partials: [slice][b][t][e] fp32 ctx (unnormalized), [slice][b][t] m/l
__device__ float g_pctx[NSLICE * Bb * Tt * Ee];   // 67 MB
__device__ float g_pm[NSLICE * Bb * Tt];
__device__ float g_pl[NSLICE * Bb * Tt];

// ---------------------------------------------------------------------------
// Helpers
// ---------------------------------------------------------------------------
__device__ __forceinline__ uint32_t smem_u32(const void* p) {
    uint32_t a;
    asm("{ .reg .u64 t; cvta.to.shared.u64 t, %1; cvt.u32.u64 %0, t; }"
        : "=r"(a) : "l"(p));
    return a;
}

__device__ __forceinline__ void mma16816(float* d, const uint32_t* a,
                                         const uint32_t* b) {
    asm volatile(
        "mma.sync.aligned.m16n8k16.row.col.f32.bf16.bf16.f32 "
        "{%0,%1,%2,%3}, {%4,%5,%6,%7}, {%8,%9}, {%0,%1,%2,%3};"
        : "+f"(d[0]), "+f"(d[1]), "+f"(d[2]), "+f"(d[3])
        : "r"(a[0]), "r"(a[1]), "r"(a[2]), "r"(a[3]), "r"(b[0]), "r"(b[1]));
}

__device__ __forceinline__ void ldsm_x4_t(uint32_t& r0, uint32_t& r1,
                                          uint32_t& r2, uint32_t& r3,
                                          uint32_t addr) {
    asm volatile("ldmatrix.sync.aligned.m8n8.x4.trans.shared.b16 "
                 "{%0,%1,%2,%3}, [%4];"
                 : "=r"(r0), "=r"(r1), "=r"(r2), "=r"(r3) : "r"(addr));
}

__device__ __forceinline__ void bsplit(float x, unsigned short& h,
                                       unsigned short& l) {
    __nv_bfloat16 hb = __float2bfloat16(x);
    __nv_bfloat16 lb = __float2bfloat16(x - __bfloat162float(hb));
    h = *(unsigned short*)&hb;
    l = *(unsigned short*)&lb;
}

__device__ __forceinline__ uint32_t pack2(unsigned short a, unsigned short b) {
    return (uint32_t)a | ((uint32_t)b << 16);
}

// ---------------------------------------------------------------------------
// Mask prologue (handles uint8 or int32 bool encodings)
// ---------------------------------------------------------------------------
__global__ void detect_lengths_kernel(const unsigned char* __restrict__ mask)
{
    __shared__ int s_flag;
    __shared__ int s_cnt[Bb];
    int tid = threadIdx.x;
    if (tid == 0) s_flag = 0;
    if (tid < Bb) s_cnt[tid] = 0;
    __syncthreads();

    int local = 0;
    for (int i = tid; i < Bb * Ss; i += 256)
        if ((i & 3) != 0 && mask[i] != 0) local = 1;
    if (local) atomicOr(&s_flag, 1);
    __syncthreads();

    bool isU8 = (s_flag != 0);
    int row = tid >> 4, part = tid & 15;
    int cnt = 0;
    if (isU8) {
        const unsigned char* p = mask + row * Ss + part * 128;
        #pragma unroll 4
        for (int e = 0; e < 128; e++) cnt += (p[e] != 0);
    } else {
        const int* p = ((const int*)mask) + row * Ss + part * 128;
        #pragma unroll 4
        for (int e = 0; e < 128; e++) cnt += (p[e] != 0);
    }
    atomicAdd(&s_cnt[row], cnt);
    __syncthreads();
    if (tid < Bb) g_lengths[tid] = s_cnt[tid];
}

// ---------------------------------------------------------------------------
// Prep: fp32 -> bf16 hi/lo for enc, dec; transposed hi/lo for weights.
// ---------------------------------------------------------------------------
__global__ void prep_convert_kernel(const float* __restrict__ enc,
                                    const float* __restrict__ dec,
                                    const float* __restrict__ Wenc,
                                    const float* __restrict__ Wfin)
{
    int tid = blockIdx.x * blockDim.x + threadIdx.x;
    int stride = gridDim.x * blockDim.x;

    const int NE4 = (Bb * Ss * Ee) / 4;
    for (int i = tid; i < NE4; i += stride) {
        float4 v = ((const float4*)enc)[i];
        ushort4 hv, lv;
        bsplit(v.x, hv.x, lv.x); bsplit(v.y, hv.y, lv.y);
        bsplit(v.z, hv.z, lv.z); bsplit(v.w, hv.w, lv.w);
        ((ushort4*)g_encH)[i] = hv;
        ((ushort4*)g_encL)[i] = lv;
    }
    const int ND4 = (Bb * Tt * Dd) / 4;
    for (int i = tid; i < ND4; i += stride) {
        float4 v = ((const float4*)dec)[i];
        ushort4 hv, lv;
        bsplit(v.x, hv.x, lv.x); bsplit(v.y, hv.y, lv.y);
        bsplit(v.z, hv.z, lv.z); bsplit(v.w, hv.w, lv.w);
        ((ushort4*)g_decH)[i] = hv;
        ((ushort4*)g_decL)[i] = lv;
    }
    for (int i = tid; i < 256 * 256; i += stride) {
        int d = i >> 8, e = i & 255;
        unsigned short h, l;
        bsplit(Wenc[e * 256 + d], h, l);
        *(unsigned short*)&g_WencTH[i] = h;
        *(unsigned short*)&g_WencTL[i] = l;
    }
    for (int i = tid; i < 256 * 512; i += stride) {
        int d = i >> 9, f = i & 511;
        unsigned short h, l;
        bsplit(Wfin[f * 256 + d], h, l);
        *(unsigned short*)&g_WfinTH[i] = h;
        *(unsigned short*)&g_WfinTL[i] = l;
    }
}

// ---------------------------------------------------------------------------
// Split-bf16 tensor-core GEMM (unchanged from round 3)
// ---------------------------------------------------------------------------
#define GSM_A_H 0
#define GSM_A_L 18432
#define GSM_B_H 36864
#define GSM_B_L 55296
#define GSM_TOTAL 73728

template<int KTOT, bool TANH>
__global__ __launch_bounds__(256, 2)
void mma_gemm_kernel(const __nv_bfloat16* __restrict__ A1H,
                     const __nv_bfloat16* __restrict__ A1L,
                     const __nv_bfloat16* __restrict__ A2H,
                     const __nv_bfloat16* __restrict__ A2L,
                     const __nv_bfloat16* __restrict__ BTH,
                     const __nv_bfloat16* __restrict__ BTL,
                     float* __restrict__ Cf,
                     __nv_bfloat16* __restrict__ CH,
                     __nv_bfloat16* __restrict__ CL)
{
    extern __shared__ char dyn[];
    __nv_bfloat16* sAH = (__nv_bfloat16*)(dyn + GSM_A_H);
    __nv_bfloat16* sAL = (__nv_bfloat16*)(dyn + GSM_A_L);
    __nv_bfloat16* sBH = (__nv_bfloat16*)(dyn + GSM_B_H);
    __nv_bfloat16* sBL = (__nv_bfloat16*)(dyn + GSM_B_L);

    int tid = threadIdx.x, lane = tid & 31, wid = tid >> 5;
    int warpM = wid & 3, warpN = wid >> 2;
    int m0 = blockIdx.y * 128, n0 = blockIdx.x * 128;
    int r = lane >> 2, cc = (lane & 3) * 2;

    float acc[2][8][4];
    #pragma unroll
    for (int i = 0; i < 2; i++)
        #pragma unroll
        for (int j = 0; j < 8; j++)
            #pragma unroll
            for (int q = 0; q < 4; q++) acc[i][j][q] = 0.f;

    for (int kc = 0; kc < KTOT; kc += 64) {
        const __nv_bfloat16* AH = A1H;
        const __nv_bfloat16* AL = A1L;
        int kcol = kc;
        if (KTOT > 256 && kc >= 256) { AH = A2H; AL = A2L; kcol = kc - 256; }

        #pragma unroll
        for (int u = 0; u < 4; u++) {
            int f = tid + u * 256;
            int rr = f >> 3, c8 = f & 7;
            *(uint4*)&sAH[rr * 72 + c8 * 8] =
                *(const uint4*)&AH[(size_t)(m0 + rr) * 256 + kcol + c8 * 8];
            *(uint4*)&sAL[rr * 72 + c8 * 8] =
                *(const uint4*)&AL[(size_t)(m0 + rr) * 256 + kcol + c8 * 8];
            *(uint4*)&sBH[rr * 72 + c8 * 8] =
                *(const uint4*)&BTH[(size_t)(n0 + rr) * KTOT + kc + c8 * 8];
            *(uint4*)&sBL[rr * 72 + c8 * 8] =
                *(const uint4*)&BTL[(size_t)(n0 + rr) * KTOT + kc + c8 * 8];
        }
        __syncthreads();

        #pragma unroll
        for (int ks = 0; ks < 4; ks++) {
            int k0 = ks * 16;
            uint32_t aH[2][4], aL[2][4];
            #pragma unroll
            for (int mt = 0; mt < 2; mt++) {
                int ar = warpM * 32 + mt * 16 + r;
                int ac = k0 + cc;
                aH[mt][0] = *(uint32_t*)&sAH[ar * 72 + ac];
                aH[mt][1] = *(uint32_t*)&sAH[(ar + 8) * 72 + ac];
                aH[mt][2] = *(uint32_t*)&sAH[ar * 72 + ac + 8];
                aH[mt][3] = *(uint32_t*)&sAH[(ar + 8) * 72 + ac + 8];
                aL[mt][0] = *(uint32_t*)&sAL[ar * 72 + ac];
                aL[mt][1] = *(uint32_t*)&sAL[(ar + 8) * 72 + ac];
                aL[mt][2] = *(uint32_t*)&sAL[ar * 72 + ac + 8];
                aL[mt][3] = *(uint32_t*)&sAL[(ar + 8) * 72 + ac + 8];
            }
            #pragma unroll
            for (int nt = 0; nt < 8; nt++) {
                int bn = warpN * 64 + nt * 8 + r;
                int bc = k0 + cc;
                uint32_t bH[2], bL[2];
                bH[0] = *(uint32_t*)&sBH[bn * 72 + bc];
                bH[1] = *(uint32_t*)&sBH[bn * 72 + bc + 8];
                bL[0] = *(uint32_t*)&sBL[bn * 72 + bc];
                bL[1] = *(uint32_t*)&sBL[bn * 72 + bc + 8];
                #pragma unroll
                for (int mt = 0; mt < 2; mt++) {
                    mma16816(acc[mt][nt], aH[mt], bH);
                    mma16816(acc[mt][nt], aH[mt], bL);
                    mma16816(acc[mt][nt], aL[mt], bH);
                }
            }
        }
        __syncthreads();
    }

    #pragma unroll
    for (int mt = 0; mt < 2; mt++) {
        #pragma unroll
        for (int nt = 0; nt < 8; nt++) {
            int m = m0 + warpM * 32 + mt * 16 + r;
            int n = n0 + warpN * 64 + nt * 8 + cc;
            float c0 = acc[mt][nt][0], c1 = acc[mt][nt][1];
            float c2 = acc[mt][nt][2], c3 = acc[mt][nt][3];
            if (TANH) {
                float2 v0 = make_float2(tanhf(c0), tanhf(c1));
                float2 v1 = make_float2(tanhf(c2), tanhf(c3));
                *(float2*)&Cf[(size_t)m * 256 + n] = v0;
                *(float2*)&Cf[(size_t)(m + 8) * 256 + n] = v1;
            } else {
                unsigned short h0, l0, h1, l1, h2, l2, h3, l3;
                bsplit(c0, h0, l0); bsplit(c1, h1, l1);
                bsplit(c2, h2, l2); bsplit(c3, h3, l3);
                *(uint32_t*)&CH[(size_t)m * 256 + n] = pack2(h0, h1);
                *(uint32_t*)&CL[(size_t)m * 256 + n] = pack2(l0, l1);
                *(uint32_t*)&CH[(size_t)(m + 8) * 256 + n] = pack2(h2, h3);
                *(uint32_t*)&CL[(size_t)(m + 8) * 256 + n] = pack2(l2, l3);
            }
        }
    }
}

// ---------------------------------------------------------------------------
// Fused flash attention, split-KV. Block = (t-tile 64, batch, S-slice of 512).
// Writes unnormalized partial (m, l, ctx fp32) per slice; combine merges.
// ---------------------------------------------------------------------------
#define ASM_A_H   0
#define ASM_A_L   9216
#define ASM_B_H   18432
#define ASM_B_L   27648
#define ASM_S     36864
#define ASM_ENC_H 54272
#define ASM_ENC_L 71680
#define ASM_M     89088
#define ASM_L     89344
#define ASM_SC    89600
#define ASM_TOTAL 89856

__global__ __launch_bounds__(256, 2)
void attn_kernel()
{
    extern __shared__ char dyn[];
    __nv_bfloat16* sAH = (__nv_bfloat16*)(dyn + ASM_A_H);
    __nv_bfloat16* sAL = (__nv_bfloat16*)(dyn + ASM_A_L);
    __nv_bfloat16* sBH = (__nv_bfloat16*)(dyn + ASM_B_H);
    __nv_bfloat16* sBL = (__nv_bfloat16*)(dyn + ASM_B_L);
    float* sS = (float*)(dyn + ASM_S);
    __nv_bfloat16* sEH = (__nv_bfloat16*)(dyn + ASM_ENC_H);
    __nv_bfloat16* sEL = (__nv_bfloat16*)(dyn + ASM_ENC_L);
    float* mstat = (float*)(dyn + ASM_M);
    float* lstat = (float*)(dyn + ASM_L);
    float* sscale = (float*)(dyn + ASM_SC);

    uint32_t encHb = smem_u32(dyn) + ASM_ENC_H;
    uint32_t encLb = smem_u32(dyn) + ASM_ENC_L;

    int tid = threadIdx.x, lane = tid & 31, wid = tid >> 5;
    int warpT = wid & 3;
    int warpS = wid >> 2;
    int r = lane >> 2, cc = (lane & 3) * 2;
    int b = blockIdx.y;
    int t0 = blockIdx.x * 64;
    int slice = blockIdx.z;
    int len = g_lengths[b];

    int sbeg = slice * SLICE_S;
    if (sbeg >= len) return;            // empty slice: no partial, combine skips
    int send = min(sbeg + SLICE_S, len);

    if (tid < 64) { mstat[tid] = -1e30f; lstat[tid] = 0.f; }

    float ctx[2][8][4];
    #pragma unroll
    for (int i = 0; i < 2; i++)
        #pragma unroll
        for (int j = 0; j < 8; j++)
            #pragma unroll
            for (int q = 0; q < 4; q++) ctx[i][j][q] = 0.f;
    __syncthreads();

    int rowL = tid >> 2, l4 = tid & 3;
    size_t decBase = ((size_t)b * Tt + t0) * 256;
    size_t encBase = (size_t)b * Ss * 256;

    for (int s0 = sbeg; s0 < send; s0 += 64) {
        // ---------------- score GEMM: 64t x 64s, K=256 in 4 chunks ---------
        float sacc[4][4];
        #pragma unroll
        for (int j = 0; j < 4; j++)
            #pragma unroll
            for (int q = 0; q < 4; q++) sacc[j][q] = 0.f;

        for (int kch = 0; kch < 4; kch++) {
            int kc = kch * 64;
            #pragma unroll
            for (int u = 0; u < 2; u++) {
                int f = tid + u * 256;
                int rr = f >> 3, c8 = f & 7;
                *(uint4*)&sAH[rr * 72 + c8 * 8] =
                    *(const uint4*)&g_decH[decBase + (size_t)rr * 256 + kc + c8 * 8];
                *(uint4*)&sAL[rr * 72 + c8 * 8] =
                    *(const uint4*)&g_decL[decBase + (size_t)rr * 256 + kc + c8 * 8];
                *(uint4*)&sBH[rr * 72 + c8 * 8] =
                    *(const uint4*)&g_projH[encBase + (size_t)(s0 + rr) * 256 + kc + c8 * 8];
                *(uint4*)&sBL[rr * 72 + c8 * 8] =
                    *(const uint4*)&g_projL[encBase + (size_t)(s0 + rr) * 256 + kc + c8 * 8];
            }
            __syncthreads();

            #pragma unroll
            for (int ks = 0; ks < 4; ks++) {
                int k0 = ks * 16;
                int ar = warpT * 16 + r;
                int ac = k0 + cc;
                uint32_t aH[4], aL[4];
                aH[0] = *(uint32_t*)&sAH[ar * 72 + ac];
                aH[1] = *(uint32_t*)&sAH[(ar + 8) * 72 + ac];
                aH[2] = *(uint32_t*)&sAH[ar * 72 + ac + 8];
                aH[3] = *(uint32_t*)&sAH[(ar + 8) * 72 + ac + 8];
                aL[0] = *(uint32_t*)&sAL[ar * 72 + ac];
                aL[1] = *(uint32_t*)&sAL[(ar + 8) * 72 + ac];
                aL[2] = *(uint32_t*)&sAL[ar * 72 + ac + 8];
                aL[3] = *(uint32_t*)&sAL[(ar + 8) * 72 + ac + 8];
                #pragma unroll
                for (int nt = 0; nt < 4; nt++) {
                    int bn = warpS * 32 + nt * 8 + r;
                    uint32_t bH[2], bL[2];
                    bH[0] = *(uint32_t*)&sBH[bn * 72 + ac];
                    bH[1] = *(uint32_t*)&sBH[bn * 72 + ac + 8];
                    bL[0] = *(uint32_t*)&sBL[bn * 72 + ac];
                    bL[1] = *(uint32_t*)&sBL[bn * 72 + ac + 8];
                    mma16816(sacc[nt], aH, bH);
                    mma16816(sacc[nt], aH, bL);
                    mma16816(sacc[nt], aL, bH);
                }
            }
            __syncthreads();
        }

        #pragma unroll
        for (int nt = 0; nt < 4; nt++) {
            int tr = warpT * 16 + r;
            int sc = warpS * 32 + nt * 8 + cc;
            *(float2*)&sS[tr * 68 + sc] = make_float2(sacc[nt][0], sacc[nt][1]);
            *(float2*)&sS[(tr + 8) * 68 + sc] = make_float2(sacc[nt][2], sacc[nt][3]);
        }
        __syncthreads();

        // ---------------- online softmax -----------------------------------
        float v[16];
        float tmax = -1e30f;
        int sbase = l4 * 16;
        #pragma unroll
        for (int q = 0; q < 16; q++) {
            int sc = sbase + q;
            float val = (s0 + sc < len) ? sS[rowL * 68 + sc] : -1e30f;
            v[q] = val;
            tmax = fmaxf(tmax, val);
        }
        tmax = fmaxf(tmax, __shfl_xor_sync(0xffffffffu, tmax, 1));
        tmax = fmaxf(tmax, __shfl_xor_sync(0xffffffffu, tmax, 2));
        float mOld = mstat[rowL];
        float mNew = fmaxf(mOld, tmax);
        float sum = 0.f;
        #pragma unroll
        for (int q = 0; q < 16; q++) {
            v[q] = __expf(v[q] - mNew);
            sum += v[q];
        }
        sum += __shfl_xor_sync(0xffffffffu, sum, 1);
        sum += __shfl_xor_sync(0xffffffffu, sum, 2);
        float scl = __expf(mOld - mNew);
        if (l4 == 0) {
            mstat[rowL] = mNew;
            lstat[rowL] = lstat[rowL] * scl + sum;
            sscale[rowL] = scl;
        }
        #pragma unroll
        for (int q = 0; q < 16; q++) {
            unsigned short h, l;
            bsplit(v[q], h, l);
            *(unsigned short*)&sAH[rowL * 72 + sbase + q] = h;
            *(unsigned short*)&sAL[rowL * 72 + sbase + q] = l;
        }
        __syncthreads();

        float f0 = sscale[warpT * 16 + r];
        float f1 = sscale[warpT * 16 + r + 8];
        #pragma unroll
        for (int i = 0; i < 2; i++)
            #pragma unroll
            for (int j = 0; j < 8; j++) {
                ctx[i][j][0] *= f0; ctx[i][j][1] *= f0;
                ctx[i][j][2] *= f1; ctx[i][j][3] *= f1;
            }

        // ---------------- context GEMM: ctx += p @ enc ---------------------
        #pragma unroll
        for (int ec = 0; ec < 2; ec++) {
            #pragma unroll
            for (int u = 0; u < 4; u++) {
                int f = tid + u * 256;
                int rr = f >> 4, c8 = f & 15;
                *(uint4*)&sEH[rr * 136 + c8 * 8] =
                    *(const uint4*)&g_encH[encBase + (size_t)(s0 + rr) * 256 + ec * 128 + c8 * 8];
                *(uint4*)&sEL[rr * 136 + c8 * 8] =
                    *(const uint4*)&g_encL[encBase + (size_t)(s0 + rr) * 256 + ec * 128 + c8 * 8];
            }
            __syncthreads();

            #pragma unroll
            for (int ks = 0; ks < 4; ks++) {
                int k0 = ks * 16;
                int ar = warpT * 16 + r;
                int ac = k0 + cc;
                uint32_t aH[4], aL[4];
                aH[0] = *(uint32_t*)&sAH[ar * 72 + ac];
                aH[1] = *(uint32_t*)&sAH[(ar + 8) * 72 + ac];
                aH[2] = *(uint32_t*)&sAH[ar * 72 + ac + 8];
                aH[3] = *(uint32_t*)&sAH[(ar + 8) * 72 + ac + 8];
                aL[0] = *(uint32_t*)&sAL[ar * 72 + ac];
                aL[1] = *(uint32_t*)&sAL[(ar + 8) * 72 + ac];
                aL[2] = *(uint32_t*)&sAL[ar * 72 + ac + 8];
                aL[3] = *(uint32_t*)&sAL[(ar + 8) * 72 + ac + 8];
                uint32_t lrow = (uint32_t)(k0 + (lane & 15));
                uint32_t lcol0 = (uint32_t)(warpS * 64 + ((lane >> 4) << 3));
                #pragma unroll
                for (int pair = 0; pair < 4; pair++) {
                    uint32_t off = (lrow * 136 + lcol0 + pair * 16) * 2;
                    uint32_t bh0, bh1, bh2, bh3, bl0, bl1, bl2, bl3;
                    ldsm_x4_t(bh0, bh1, bh2, bh3, encHb + off);
                    ldsm_x4_t(bl0, bl1, bl2, bl3, encLb + off);
                    uint32_t bH0[2] = {bh0, bh1}, bH1[2] = {bh2, bh3};
                    uint32_t bL0[2] = {bl0, bl1}, bL1[2] = {bl2, bl3};
                    int nt = pair * 2;
                    mma16816(ctx[ec][nt], aH, bH0);
                    mma16816(ctx[ec][nt], aH, bL0);
                    mma16816(ctx[ec][nt], aL, bH0);
                    mma16816(ctx[ec][nt + 1], aH, bH1);
                    mma16816(ctx[ec][nt + 1], aH, bL1);
                    mma16816(ctx[ec][nt + 1], aL, bH1);
                }
            }
            __syncthreads();
        }
    }

    // ---------------- write partial (m, l, unnormalized ctx) ----------------
    size_t pmBase = (((size_t)slice * Bb + b) * Tt) + t0;
    if (tid < 64) {
        g_pm[pmBase + tid] = mstat[tid];
        g_pl[pmBase + tid] = lstat[tid];
    }
    int t = t0 + warpT * 16 + r;
    size_t obase = (((size_t)slice * Bb + b) * Tt + t) * 256;
    #pragma unroll
    for (int ec = 0; ec < 2; ec++) {
        #pragma unroll
        for (int nt = 0; nt < 8; nt++) {
            int e = ec * 128 + warpS * 64 + nt * 8 + cc;
            *(float2*)&g_pctx[obase + e] =
                make_float2(ctx[ec][nt][0], ctx[ec][nt][1]);
            *(float2*)&g_pctx[obase + 8 * 256 + e] =
                make_float2(ctx[ec][nt][2], ctx[ec][nt][3]);
        }
    }
}

// ---------------------------------------------------------------------------
// Combine: merge slice partials -> normalized ctx, split to bf16 hi/lo.
// Block = (t-tile 64, batch), 256 threads.
// ---------------------------------------------------------------------------
__global__ __launch_bounds__(256)
void combine_kernel()
{
    __shared__ float w[64][4];
    int tid = threadIdx.x;
    int b = blockIdx.y;
    int t0 = blockIdx.x * 64;
    int len = g_lengths[b];
    int nsl = min(NSLICE, (len + SLICE_S - 1) / SLICE_S);

    if (tid < 64) {
        int t = t0 + tid;
        float mv[4], lv[4];
        float M = -1e30f;
        for (int s = 0; s < nsl; s++) {
            size_t off = (((size_t)s * Bb + b) * Tt) + t;
            mv[s] = g_pm[off];
            lv[s] = g_pl[off];
            M = fmaxf(M, mv[s]);
        }
        float L = 0.f;
        float ws[4];
        for (int s = 0; s < nsl; s++) {
            float e = __expf(mv[s] - M);
            ws[s] = e;
            L += e * lv[s];
        }
        float inv = 1.0f / L;
        for (int s = 0; s < 4; s++)
            w[tid][s] = (s < nsl) ? ws[s] * inv : 0.f;
    }
    __syncthreads();

    int r = tid >> 2, c0 = (tid & 3) * 64;
    int t = t0 + r;
    float wr[4] = {w[r][0], w[r][1], w[r][2], w[r][3]};
    size_t eBase = (((size_t)b) * Tt + t) * 256 + c0;   // output index
    #pragma unroll 4
    for (int e = 0; e < 64; e += 4) {
        float4 acc = make_float4(0.f, 0.f, 0.f, 0.f);
        for (int s = 0; s < nsl; s++) {
            size_t off = (((size_t)s * Bb + b) * Tt + t) * 256 + c0 + e;
            float4 v = *(const float4*)&g_pctx[off];
            acc.x += wr[s] * v.x; acc.y += wr[s] * v.y;
            acc.z += wr[s] * v.z; acc.w += wr[s] * v.w;
        }
        unsigned short h0, l0, h1, l1, h2, l2, h3, l3;
        bsplit(acc.x, h0, l0); bsplit(acc.y, h1, l1);
        bsplit(acc.z, h2, l2); bsplit(acc.w, h3, l3);
        *(uint32_t*)&g_ctxH[eBase + e] = pack2(h0, h1);
        *(uint32_t*)&g_ctxH[eBase + e + 2] = pack2(h2, h3);
        *(uint32_t*)&g_ctxL[eBase + e] = pack2(l0, l1);
        *(uint32_t*)&g_ctxL[eBase + e + 2] = pack2(l2, l3);
    }
}

// ---------------------------------------------------------------------------
extern "C" void kernel_launch(void* const* d_in, const int* in_sizes, int n_in,
                              void* d_out, int out_size)
{
    (void)in_sizes; (void)n_in; (void)out_size;
    const float* enc = (const float*)d_in[0];
    const float* dec = (const float*)d_in[1];
    const unsigned char* mask = (const unsigned char*)d_in[2];
    const float* W_enc = (const float*)d_in[3];
    const float* W_fin = (const float*)d_in[4];
    float* out = (float*)d_out;

    void *pEncH, *pEncL, *pDecH, *pDecL, *pProjH, *pProjL;
    void *pCtxH, *pCtxL, *pWeH, *pWeL, *pWfH, *pWfL;
    cudaGetSymbolAddress(&pEncH, g_encH);
    cudaGetSymbolAddress(&pEncL, g_encL);
    cudaGetSymbolAddress(&pDecH, g_decH);
    cudaGetSymbolAddress(&pDecL, g_decL);
    cudaGetSymbolAddress(&pProjH, g_projH);
    cudaGetSymbolAddress(&pProjL, g_projL);
    cudaGetSymbolAddress(&pCtxH, g_ctxH);
    cudaGetSymbolAddress(&pCtxL, g_ctxL);
    cudaGetSymbolAddress(&pWeH, g_WencTH);
    cudaGetSymbolAddress(&pWeL, g_WencTL);
    cudaGetSymbolAddress(&pWfH, g_WfinTH);
    cudaGetSymbolAddress(&pWfL, g_WfinTL);

    cudaFuncSetAttribute((const void*)mma_gemm_kernel<256, false>,
                         cudaFuncAttributeMaxDynamicSharedMemorySize, GSM_TOTAL);
    cudaFuncSetAttribute((const void*)mma_gemm_kernel<512, true>,
                         cudaFuncAttributeMaxDynamicSharedMemorySize, GSM_TOTAL);
    cudaFuncSetAttribute((const void*)attn_kernel,
                         cudaFuncAttributeMaxDynamicSharedMemorySize, ASM_TOTAL);

    detect_lengths_kernel<<<1, 256>>>(mask);
    prep_convert_kernel<<<1024, 256>>>(enc, dec, W_enc, W_fin);

    // GEMM1: proj = enc @ W_enc  -> bf16 hi/lo
    dim3 g1(2, 256);
    mma_gemm_kernel<256, false><<<g1, 256, GSM_TOTAL>>>(
        (const __nv_bfloat16*)pEncH, (const __nv_bfloat16*)pEncL,
        nullptr, nullptr,
        (const __nv_bfloat16*)pWeH, (const __nv_bfloat16*)pWeL,
        nullptr, (__nv_bfloat16*)pProjH, (__nv_bfloat16*)pProjL);

    // Attention with split-KV slices
    dim3 g2(Tt / 64, Bb, NSLICE);
    attn_kernel<<<g2, 256, ASM_TOTAL>>>();

    // Combine slice partials into bf16 hi/lo context
    dim3 gc(Tt / 64, Bb);
    combine_kernel<<<gc, 256>>>();

    // GEMM3: out = tanh([ctx | dec] @ W_fin)
    dim3 g3(2, 128);
    mma_gemm_kernel<512, true><<<g3, 256, GSM_TOTAL>>>(
        (const __nv_bfloat16*)pCtxH, (const __nv_bfloat16*)pCtxL,
        (const __nv_bfloat16*)pDecH, (const __nv_bfloat16*)pDecL,
        (const __nv_bfloat16*)pWfH, (const __nv_bfloat16*)pWfL,
        out, nullptr, nullptr);
}